// round 13
// baseline (speedup 1.0000x reference)
#include <cuda_runtime.h>
#include <cuda_fp16.h>
#include <cstdint>
#include <math.h>

// ---------------------------------------------------------------- constants
#define B_ 4
#define S_ 8192
#define D_ 1024
#define H_ 1024
#define O_ 1024

#define BM 128                 // s-rows per CTA tile
#define BN 64                  // j-cols per CTA tile (per gate; 3 gates)
#define BK 32                  // k per pipeline chunk
#define NCHUNK (D_ / BK)       // 32
#define NTH 512                // 16 warps (4 per SMSP)

#define ROWB 80                // fp16 A/B smem row stride (64 data + 16 pad)
#define RAWROW 144             // fp32 raw A row stride (128 data + 16 pad, 16B-aligned)

#define RAW_TILE (BM * RAWROW)         // 18432
#define A_TILE (BM * ROWB)             // 10240
#define B_TILE (BN * ROWB)             // 5120
#define BSTAGE (3 * B_TILE)            // 15360

#define RAW_OFF 0
#define A16_OFF (2 * RAW_TILE)                 // 36864
#define B_OFF   (A16_OFF + 2 * A_TILE)         // 57344
#define SMEM_DYN (B_OFF + 3 * BSTAGE)          // 103424

#define MTILES (B_ * S_ / BM)  // 256
#define JTILES (H_ / BN)       // 16
#define MT_PER_B (S_ / BM)     // 64

// ---------------------------------------------------------------- scratch
__device__ __half g_wh[3 * H_ * D_];
__device__ float g_pacc[B_][MT_PER_B][H_];
__device__ float g_sig[B_][H_];
__device__ float g_hT[B_][H_];

// ---------------------------------------------------------------- helpers
__device__ __forceinline__ uint32_t smem_u32(const void* p) {
    uint32_t a;
    asm("{ .reg .u64 t; cvta.to.shared.u64 t, %1; cvt.u32.u64 %0, t; }"
        : "=r"(a) : "l"(p));
    return a;
}

__device__ __forceinline__ void cp_async16(uint32_t dst, const void* src) {
    size_t g = (size_t)__cvta_generic_to_global(src);
    asm volatile("cp.async.cg.shared.global [%0], [%1], 16;\n"
                 :: "r"(dst), "l"(g));
}

__device__ __forceinline__ void ldsm_x4(uint32_t* r, uint32_t addr) {
    asm volatile("ldmatrix.sync.aligned.m8n8.x4.shared.b16 {%0,%1,%2,%3}, [%4];"
                 : "=r"(r[0]), "=r"(r[1]), "=r"(r[2]), "=r"(r[3]) : "r"(addr));
}

__device__ __forceinline__ void mma16816(float* c, const uint32_t* a,
                                         uint32_t b0, uint32_t b1) {
    asm volatile(
        "mma.sync.aligned.m16n8k16.row.col.f32.f16.f16.f32 "
        "{%0,%1,%2,%3}, {%4,%5,%6,%7}, {%8,%9}, {%0,%1,%2,%3};"
        : "+f"(c[0]), "+f"(c[1]), "+f"(c[2]), "+f"(c[3])
        : "r"(a[0]), "r"(a[1]), "r"(a[2]), "r"(a[3]), "r"(b0), "r"(b1));
}

// ---------------------------------------------------------------- prep: w fp32 -> fp16
#define NW4 (3 * H_ * D_ / 4)      // 786432

__global__ __launch_bounds__(256) void k_cvt_w(const float* __restrict__ w) {
    int i = blockIdx.x * 256 + threadIdx.x;
    if (i >= NW4) return;
    float4 v = ((const float4*)w)[i];
    unsigned short hb[4];
    hb[0] = __half_as_ushort(__float2half_rn(v.x));
    hb[1] = __half_as_ushort(__float2half_rn(v.y));
    hb[2] = __half_as_ushort(__float2half_rn(v.z));
    hb[3] = __half_as_ushort(__float2half_rn(v.w));
    uint2 hp;
    hp.x = (uint32_t)hb[0] | ((uint32_t)hb[1] << 16);
    hp.y = (uint32_t)hb[2] | ((uint32_t)hb[3] << 16);
    ((uint2*)g_wh)[i] = hp;
}

// ---------------------------------------------------------------- stage loader (raw A fp32 + B fp16)
__device__ __forceinline__ void load_group(uint32_t sb0, int ck,
                                           const float* __restrict__ x,
                                           size_t xrow0, int j0, int tid) {
    const int k0 = ck * BK;
    const uint32_t raw = sb0 + RAW_OFF + (ck & 1) * RAW_TILE;
    const uint32_t bb = sb0 + B_OFF + (ck % 3) * BSTAGE;
    // raw A: 128 rows x 8 x 16B = 1024 ; B: 3 gates x 64 rows x 4 x 16B = 768
#pragma unroll
    for (int it = 0; it < 4; ++it) {
        int idx = tid + it * NTH;
        if (it == 3 && idx >= 1792) break;
        if (idx < 1024) {
            int r = idx >> 3, c = idx & 7;
            const void* src = x + xrow0 + (size_t)r * D_ + k0 + c * 4;
            cp_async16(raw + r * RAWROW + c * 16, src);
        } else {
            int bidx = idx - 1024;
            int g = bidx >> 8;
            int rr = bidx & 255;
            int r = rr >> 2, c = rr & 3;
            const void* src = g_wh + (size_t)(g * H_ + j0 + r) * D_ + k0 + c * 8;
            cp_async16(bb + g * B_TILE + r * ROWB + c * 16, src);
        }
    }
    asm volatile("cp.async.commit_group;" ::: "memory");
}

// ---------------------------------------------------------------- in-kernel fp32->fp16 convert
__device__ __forceinline__ void convert_a(uint32_t sb0, int ck, int tid) {
    const uint32_t raw = sb0 + RAW_OFF + (ck & 1) * RAW_TILE;
    const uint32_t a16 = sb0 + A16_OFF + (ck & 1) * A_TILE;
    const int r = tid >> 2;            // 0..127
    const int c = tid & 3;             // 8-float chunk
    float4 u, v;
    uint32_t src = raw + r * RAWROW + c * 32;
    asm volatile("ld.shared.v4.f32 {%0,%1,%2,%3}, [%4];"
                 : "=f"(u.x), "=f"(u.y), "=f"(u.z), "=f"(u.w) : "r"(src));
    asm volatile("ld.shared.v4.f32 {%0,%1,%2,%3}, [%4];"
                 : "=f"(v.x), "=f"(v.y), "=f"(v.z), "=f"(v.w) : "r"(src + 16));
    __half2 h0 = __floats2half2_rn(u.x, u.y);
    __half2 h1 = __floats2half2_rn(u.z, u.w);
    __half2 h2 = __floats2half2_rn(v.x, v.y);
    __half2 h3 = __floats2half2_rn(v.z, v.w);
    uint32_t dst = a16 + r * ROWB + c * 16;
    asm volatile("st.shared.v4.b32 [%0], {%1,%2,%3,%4};"
                 :: "r"(dst), "r"(*(uint32_t*)&h0), "r"(*(uint32_t*)&h1),
                    "r"(*(uint32_t*)&h2), "r"(*(uint32_t*)&h3));
}

// ---------------------------------------------------------------- main fused GEMM+reduce
extern __shared__ __align__(128) char dynsmem[];

__global__ __launch_bounds__(NTH, 1) void k1_mma(const float* __restrict__ x) {
    __shared__ float jacc[4][BN];

    const int tid = threadIdx.x;
    const int wid = tid >> 5;
    const int lane = tid & 31;
    const int wm = wid >> 2;            // 0..3 (32 rows each)
    const int wn = wid & 3;             // 0..3 (16 cols each)
    const int jt = blockIdx.x;          // 0..15
    const int mt = blockIdx.y;          // 0..255
    const int b = mt >> 6;
    const int mtb = mt & 63;
    const int j0 = jt * BN;

    const uint32_t sb0 = smem_u32(dynsmem);
    const size_t xrow0 = (size_t)mt * BM * D_;

    float acc[3][2][2][4];
#pragma unroll
    for (int g = 0; g < 3; ++g)
#pragma unroll
        for (int mf = 0; mf < 2; ++mf)
#pragma unroll
            for (int nf = 0; nf < 2; ++nf)
#pragma unroll
                for (int q = 0; q < 4; ++q) acc[g][mf][nf][q] = 0.0f;

    // prologue: stage groups 0,1; convert A(0)
    load_group(sb0, 0, x, xrow0, j0, tid);
    load_group(sb0, 1, x, xrow0, j0, tid);
    asm volatile("cp.async.wait_group 1;" ::: "memory");
    __syncthreads();
    convert_a(sb0, 0, tid);

    const uint32_t a_rowsel = (wm * 32 + (lane & 15)) * ROWB +
                              ((lane >> 4) << 4);
    const uint32_t b_rowsel = (wn * 16 + (lane & 15)) * ROWB +
                              ((lane >> 4) << 4);

    for (int ck = 0; ck < NCHUNK; ++ck) {
        __syncthreads();   // A16(ck) conversion + raw-buffer reuse safety

        if (ck + 2 < NCHUNK)
            load_group(sb0, ck + 2, x, xrow0, j0, tid);

        if (ck + 1 < NCHUNK) {
            if (ck + 2 < NCHUNK) {
                asm volatile("cp.async.wait_group 1;" ::: "memory");
            } else {
                asm volatile("cp.async.wait_group 0;" ::: "memory");
            }
            convert_a(sb0, ck + 1, tid);   // hides under MMA(ck) via warp arb
        }

        const uint32_t abuf = sb0 + A16_OFF + (ck & 1) * A_TILE;
        const uint32_t bbuf = sb0 + B_OFF + (ck % 3) * BSTAGE;

#pragma unroll
        for (int ks = 0; ks < 2; ++ks) {
            const uint32_t koff = ks * 32;
            uint32_t ah[2][4];
#pragma unroll
            for (int mf = 0; mf < 2; ++mf)
                ldsm_x4(ah[mf], abuf + a_rowsel + mf * (16 * ROWB) + koff);
#pragma unroll
            for (int g = 0; g < 3; ++g) {
                uint32_t bq[4];   // r0=nf0.b0 r1=nf1.b0 r2=nf0.b1 r3=nf1.b1
                ldsm_x4(bq, bbuf + g * B_TILE + b_rowsel + koff);
#pragma unroll
                for (int mf = 0; mf < 2; ++mf) {
                    mma16816(acc[g][mf][0], ah[mf], bq[0], bq[2]);
                    mma16816(acc[g][mf][1], ah[mf], bq[1], bq[3]);
                }
            }
        }
    }

    // ---- epilogue: elementwise + reduce over s rows
    float vloc[2][2] = {{0.f, 0.f}, {0.f, 0.f}};   // [nf][q&1]
#pragma unroll
    for (int mf = 0; mf < 2; ++mf)
#pragma unroll
        for (int nf = 0; nf < 2; ++nf)
#pragma unroll
            for (int q = 0; q < 4; ++q) {
                float zf = acc[0][mf][nf][q];
                float zi = acc[1][mf][nf][q];
                float zh = acc[2][mf][nf][q];
                float R = __fdividef(1.0f + __expf(-zf),
                                     1.0f + __expf(-zi));   // exp(diff)
                float gv = (zh >= 0.0f)
                               ? (zh + 0.5f)
                               : __fdividef(1.0f, 1.0f + __expf(-zh));
                vloc[nf][q & 1] += R * gv;
                int row = wm * 32 + mf * 16 + (lane >> 2) + ((q >> 1) << 3);
                if (((mt * BM + row) & (S_ - 1)) == (S_ - 1)) {
                    int j = j0 + wn * 16 + nf * 8 + (lane & 3) * 2 + (q & 1);
                    g_sig[b][j] = __fdividef(1.0f, 1.0f + R);
                }
            }
#pragma unroll
    for (int nf = 0; nf < 2; ++nf)
#pragma unroll
        for (int q1 = 0; q1 < 2; ++q1) {
            float v = vloc[nf][q1];
            v += __shfl_xor_sync(0xffffffffu, v, 4);
            v += __shfl_xor_sync(0xffffffffu, v, 8);
            v += __shfl_xor_sync(0xffffffffu, v, 16);
            if (lane < 4) jacc[wm][wn * 16 + nf * 8 + lane * 2 + q1] = v;
        }
    __syncthreads();
    if (tid < BN)
        g_pacc[b][mtb][j0 + tid] =
            jacc[0][tid] + jacc[1][tid] + jacc[2][tid] + jacc[3][tid];
}

// ---------------------------------------------------------------- combine + out-init
__global__ __launch_bounds__(128) void k2_combine(const float* __restrict__ b_out,
                                                  float* __restrict__ out) {
    int b = blockIdx.x >> 3;
    int j = (blockIdx.x & 7) * 128 + threadIdx.x;
    float s = 0.0f;
#pragma unroll
    for (int mtb = 0; mtb < MT_PER_B; ++mtb) s += g_pacc[b][mtb][j];
    g_hT[b][j] = g_sig[b][j] * (0.5f + s);
    out[(size_t)b * O_ + j] = b_out[j];   // bias init for k3's atomics
}

// ---------------------------------------------------------------- out += hT @ w_out^T (k-split, atomic)
#define KS 16
#define KCH (H_ / KS)          // 64 k per split

__global__ __launch_bounds__(128) void k3_out(const float* __restrict__ w_out,
                                              float* __restrict__ out) {
    int o = blockIdx.x * 128 + threadIdx.x;
    int b = blockIdx.y;
    int k0 = blockIdx.z * KCH;

    __shared__ float hs[KCH];
    if (threadIdx.x < KCH) hs[threadIdx.x] = g_hT[b][k0 + threadIdx.x];
    __syncthreads();

    float acc = 0.0f;
    const float4* wr = (const float4*)(w_out + (size_t)o * H_ + k0);
#pragma unroll
    for (int q = 0; q < KCH / 4; ++q) {
        float4 w4 = wr[q];
        float4 h4 = *(const float4*)&hs[q * 4];
        acc = fmaf(w4.x, h4.x, acc);
        acc = fmaf(w4.y, h4.y, acc);
        acc = fmaf(w4.z, h4.z, acc);
        acc = fmaf(w4.w, h4.w, acc);
    }
    atomicAdd(&out[(size_t)b * O_ + o], acc);
}

// ---------------------------------------------------------------- launch
extern "C" void kernel_launch(void* const* d_in, const int* in_sizes, int n_in,
                              void* d_out, int out_size) {
    (void)in_sizes; (void)n_in; (void)out_size;
    const float* x     = (const float*)d_in[0];   // [4, 8192, 1024]
    const float* w_in  = (const float*)d_in[1];   // [3072, 1024]
    const float* w_out = (const float*)d_in[2];   // [1024, 1024]
    const float* b_out = (const float*)d_in[3];   // [1024]
    float* out = (float*)d_out;                   // [4, 1024]

    static int smem_set = 0;
    if (!smem_set) {
        cudaFuncSetAttribute(k1_mma, cudaFuncAttributeMaxDynamicSharedMemorySize,
                             SMEM_DYN);
        smem_set = 1;
    }

    k_cvt_w<<<(NW4 + 255) / 256, 256>>>(w_in);

    dim3 g1(JTILES, MTILES);
    k1_mma<<<g1, NTH, SMEM_DYN>>>(x);
    k2_combine<<<B_ * 8, 128>>>(b_out, out);
    dim3 g3(O_ / 128, B_, KS);
    k3_out<<<g3, 128>>>(w_out, out);
}

// round 14
// speedup vs baseline: 1.2943x; 1.2943x over previous
#include <cuda_runtime.h>
#include <cuda_fp16.h>
#include <cstdint>
#include <math.h>

// ---------------------------------------------------------------- constants
#define B_ 4
#define S_ 8192
#define D_ 1024
#define H_ 1024
#define O_ 1024

#define BM 128                 // s-rows per CTA tile
#define BN 64                  // j-cols per CTA tile (per gate; 3 gates)
#define BK 32                  // k per pipeline chunk
#define NCHUNK (D_ / BK)       // 32
#define NSTAGE 4
#define NTH 512                // 16 warps (4 per SMSP)

#define ROWB 80                // padded smem row stride bytes (64 data + 16)
#define A_TILE (BM * ROWB)     // 10240
#define B_TILE (BN * ROWB)     // 5120
#define B_OFF  A_TILE
#define STAGE  (A_TILE + 3 * B_TILE)       // 25600
#define SMEM_DYN (NSTAGE * STAGE)          // 102400

#define MTILES (B_ * S_ / BM)  // 256
#define JTILES (H_ / BN)       // 16
#define MT_PER_B (S_ / BM)     // 64

// ---------------------------------------------------------------- scratch
__device__ __half g_xh[B_ * S_ * D_];
__device__ __half g_wh[3 * H_ * D_];
__device__ float g_pacc[B_][MT_PER_B][H_];
__device__ float g_sig[B_][H_];
__device__ float g_hT[B_][H_];

// ---------------------------------------------------------------- helpers
__device__ __forceinline__ uint32_t smem_u32(const void* p) {
    uint32_t a;
    asm("{ .reg .u64 t; cvta.to.shared.u64 t, %1; cvt.u32.u64 %0, t; }"
        : "=r"(a) : "l"(p));
    return a;
}

__device__ __forceinline__ void cp_async16(uint32_t dst, const void* src) {
    size_t g = (size_t)__cvta_generic_to_global(src);
    asm volatile("cp.async.cg.shared.global [%0], [%1], 16;\n"
                 :: "r"(dst), "l"(g));
}

__device__ __forceinline__ void ldsm_x4(uint32_t* r, uint32_t addr) {
    asm volatile("ldmatrix.sync.aligned.m8n8.x4.shared.b16 {%0,%1,%2,%3}, [%4];"
                 : "=r"(r[0]), "=r"(r[1]), "=r"(r[2]), "=r"(r[3]) : "r"(addr));
}

__device__ __forceinline__ void mma16816(float* c, const uint32_t* a,
                                         uint32_t b0, uint32_t b1) {
    asm volatile(
        "mma.sync.aligned.m16n8k16.row.col.f32.f16.f16.f32 "
        "{%0,%1,%2,%3}, {%4,%5,%6,%7}, {%8,%9}, {%0,%1,%2,%3};"
        : "+f"(c[0]), "+f"(c[1]), "+f"(c[2]), "+f"(c[3])
        : "r"(a[0]), "r"(a[1]), "r"(a[2]), "r"(a[3]), "r"(b0), "r"(b1));
}

// ---------------------------------------------------------------- prep: fp32 -> fp16
#define NX4 (B_ * S_ * D_ / 4)     // 8388608
#define NW4 (3 * H_ * D_ / 4)      // 786432
#define NC4 (NX4 + NW4)            // 9175040
#define CVT_VPT 4
#define CVT_TILE (512 * CVT_VPT)   // 2048 float4 per block

__global__ __launch_bounds__(512) void k_cvt_all(const float* __restrict__ x,
                                                 const float* __restrict__ w) {
    int base = blockIdx.x * CVT_TILE + threadIdx.x;
#pragma unroll
    for (int v = 0; v < CVT_VPT; ++v) {
        int i = base + v * 512;
        if (i >= NC4) return;
        const float* src;
        __half* dst;
        int idx;
        if (i < NX4) {
            src = x; dst = g_xh; idx = i;
        } else {
            src = w; dst = g_wh; idx = i - NX4;
        }
        float4 u = ((const float4*)src)[idx];
        unsigned short hb[4];
        hb[0] = __half_as_ushort(__float2half_rn(u.x));
        hb[1] = __half_as_ushort(__float2half_rn(u.y));
        hb[2] = __half_as_ushort(__float2half_rn(u.z));
        hb[3] = __half_as_ushort(__float2half_rn(u.w));
        uint2 hp;
        hp.x = (uint32_t)hb[0] | ((uint32_t)hb[1] << 16);
        hp.y = (uint32_t)hb[2] | ((uint32_t)hb[3] << 16);
        ((uint2*)dst)[idx] = hp;
    }
}

// ---------------------------------------------------------------- stage loader
__device__ __forceinline__ void load_stage(uint32_t sb, int k0, size_t xrow0,
                                           int j0, int tid) {
    // A: 128 rows x 4 chunks = 512 ; B: 3 gates x 64 rows x 4 = 768 ; 1280 total
#pragma unroll
    for (int it = 0; it < 3; ++it) {
        int idx = tid + it * NTH;
        if (it == 2 && idx >= 1280) break;
        if (idx < 512) {
            int r = idx >> 2, c = idx & 3;
            const void* src = g_xh + xrow0 + (size_t)r * D_ + k0 + c * 8;
            cp_async16(sb + r * ROWB + c * 16, src);
        } else {
            int bidx = idx - 512;
            int g = bidx >> 8;
            int rr = bidx & 255;
            int r = rr >> 2, c = rr & 3;
            const void* src = g_wh + (size_t)(g * H_ + j0 + r) * D_ + k0 + c * 8;
            cp_async16(sb + B_OFF + g * B_TILE + r * ROWB + c * 16, src);
        }
    }
    asm volatile("cp.async.commit_group;" ::: "memory");
}

// ---------------------------------------------------------------- main fused GEMM+reduce
extern __shared__ __align__(128) char dynsmem[];

__global__ __launch_bounds__(NTH, 1) void k1_mma(void) {
    __shared__ float jacc[4][BN];

    const int tid = threadIdx.x;
    const int wid = tid >> 5;
    const int lane = tid & 31;
    const int wm = wid >> 2;            // 0..3 (32 rows each)
    const int wn = wid & 3;             // 0..3 (16 cols each)
    const int jt = blockIdx.x;          // 0..15
    const int mt = blockIdx.y;          // 0..255
    const int b = mt >> 6;
    const int mtb = mt & 63;
    const int j0 = jt * BN;

    const uint32_t sb0 = smem_u32(dynsmem);
    const size_t xrow0 = (size_t)mt * BM * D_;

    float acc[3][2][2][4];
#pragma unroll
    for (int g = 0; g < 3; ++g)
#pragma unroll
        for (int mf = 0; mf < 2; ++mf)
#pragma unroll
            for (int nf = 0; nf < 2; ++nf)
#pragma unroll
                for (int q = 0; q < 4; ++q) acc[g][mf][nf][q] = 0.0f;

    load_stage(sb0 + 0 * STAGE, 0 * BK, xrow0, j0, tid);
    load_stage(sb0 + 1 * STAGE, 1 * BK, xrow0, j0, tid);
    load_stage(sb0 + 2 * STAGE, 2 * BK, xrow0, j0, tid);

    const uint32_t a_rowsel = (wm * 32 + (lane & 15)) * ROWB +
                              ((lane >> 4) << 4);
    const uint32_t b_rowsel = (wn * 16 + (lane & 15)) * ROWB +
                              ((lane >> 4) << 4);

    for (int ck = 0; ck < NCHUNK; ++ck) {
        if (ck <= NCHUNK - 3) {
            asm volatile("cp.async.wait_group 2;" ::: "memory");
        } else if (ck == NCHUNK - 2) {
            asm volatile("cp.async.wait_group 1;" ::: "memory");
        } else {
            asm volatile("cp.async.wait_group 0;" ::: "memory");
        }
        __syncthreads();

        if (ck + 3 < NCHUNK) {
            load_stage(sb0 + ((ck + 3) % NSTAGE) * STAGE, (ck + 3) * BK, xrow0,
                       j0, tid);
        }

        const uint32_t sb = sb0 + (ck % NSTAGE) * STAGE;

#pragma unroll
        for (int ks = 0; ks < 2; ++ks) {
            const uint32_t koff = ks * 32;
            uint32_t ah[2][4];
#pragma unroll
            for (int mf = 0; mf < 2; ++mf)
                ldsm_x4(ah[mf], sb + a_rowsel + mf * (16 * ROWB) + koff);
#pragma unroll
            for (int g = 0; g < 3; ++g) {
                uint32_t bq[4];   // r0=nf0.b0 r1=nf1.b0 r2=nf0.b1 r3=nf1.b1
                ldsm_x4(bq, sb + B_OFF + g * B_TILE + b_rowsel + koff);
#pragma unroll
                for (int mf = 0; mf < 2; ++mf) {
                    mma16816(acc[g][mf][0], ah[mf], bq[0], bq[2]);
                    mma16816(acc[g][mf][1], ah[mf], bq[1], bq[3]);
                }
            }
        }
    }

    // ---- epilogue: elementwise + reduce over s rows
    float vloc[2][2] = {{0.f, 0.f}, {0.f, 0.f}};   // [nf][q&1]
#pragma unroll
    for (int mf = 0; mf < 2; ++mf)
#pragma unroll
        for (int nf = 0; nf < 2; ++nf)
#pragma unroll
            for (int q = 0; q < 4; ++q) {
                float zf = acc[0][mf][nf][q];
                float zi = acc[1][mf][nf][q];
                float zh = acc[2][mf][nf][q];
                float R = __fdividef(1.0f + __expf(-zf),
                                     1.0f + __expf(-zi));   // exp(diff)
                float gv = (zh >= 0.0f)
                               ? (zh + 0.5f)
                               : __fdividef(1.0f, 1.0f + __expf(-zh));
                vloc[nf][q & 1] += R * gv;
                int row = wm * 32 + mf * 16 + (lane >> 2) + ((q >> 1) << 3);
                if (((mt * BM + row) & (S_ - 1)) == (S_ - 1)) {
                    int j = j0 + wn * 16 + nf * 8 + (lane & 3) * 2 + (q & 1);
                    g_sig[b][j] = __fdividef(1.0f, 1.0f + R);
                }
            }
#pragma unroll
    for (int nf = 0; nf < 2; ++nf)
#pragma unroll
        for (int q1 = 0; q1 < 2; ++q1) {
            float v = vloc[nf][q1];
            v += __shfl_xor_sync(0xffffffffu, v, 4);
            v += __shfl_xor_sync(0xffffffffu, v, 8);
            v += __shfl_xor_sync(0xffffffffu, v, 16);
            if (lane < 4) jacc[wm][wn * 16 + nf * 8 + lane * 2 + q1] = v;
        }
    __syncthreads();
    if (tid < BN)
        g_pacc[b][mtb][j0 + tid] =
            jacc[0][tid] + jacc[1][tid] + jacc[2][tid] + jacc[3][tid];
}

// ---------------------------------------------------------------- combine + out-init
__global__ __launch_bounds__(128) void k2_combine(const float* __restrict__ b_out,
                                                  float* __restrict__ out) {
    int b = blockIdx.x >> 3;
    int j = (blockIdx.x & 7) * 128 + threadIdx.x;
    float s = 0.0f;
#pragma unroll
    for (int mtb = 0; mtb < MT_PER_B; ++mtb) s += g_pacc[b][mtb][j];
    g_hT[b][j] = g_sig[b][j] * (0.5f + s);
    out[(size_t)b * O_ + j] = b_out[j];   // bias init for k3's atomics
}

// ---------------------------------------------------------------- out += hT @ w_out^T (k-split, atomic)
#define KS 16
#define KCH (H_ / KS)          // 64 k per split

__global__ __launch_bounds__(128) void k3_out(const float* __restrict__ w_out,
                                              float* __restrict__ out) {
    int o = blockIdx.x * 128 + threadIdx.x;
    int b = blockIdx.y;
    int k0 = blockIdx.z * KCH;

    __shared__ float hs[KCH];
    if (threadIdx.x < KCH) hs[threadIdx.x] = g_hT[b][k0 + threadIdx.x];
    __syncthreads();

    float acc = 0.0f;
    const float4* wr = (const float4*)(w_out + (size_t)o * H_ + k0);
#pragma unroll
    for (int q = 0; q < KCH / 4; ++q) {
        float4 w4 = wr[q];
        float4 h4 = *(const float4*)&hs[q * 4];
        acc = fmaf(w4.x, h4.x, acc);
        acc = fmaf(w4.y, h4.y, acc);
        acc = fmaf(w4.z, h4.z, acc);
        acc = fmaf(w4.w, h4.w, acc);
    }
    atomicAdd(&out[(size_t)b * O_ + o], acc);
}

// ---------------------------------------------------------------- launch
extern "C" void kernel_launch(void* const* d_in, const int* in_sizes, int n_in,
                              void* d_out, int out_size) {
    (void)in_sizes; (void)n_in; (void)out_size;
    const float* x     = (const float*)d_in[0];   // [4, 8192, 1024]
    const float* w_in  = (const float*)d_in[1];   // [3072, 1024]
    const float* w_out = (const float*)d_in[2];   // [1024, 1024]
    const float* b_out = (const float*)d_in[3];   // [1024]
    float* out = (float*)d_out;                   // [4, 1024]

    static int smem_set = 0;
    if (!smem_set) {
        cudaFuncSetAttribute(k1_mma, cudaFuncAttributeMaxDynamicSharedMemorySize,
                             SMEM_DYN);
        smem_set = 1;
    }

    k_cvt_all<<<(NC4 + CVT_TILE - 1) / CVT_TILE, 512>>>(x, w_in);

    dim3 g1(JTILES, MTILES);
    k1_mma<<<g1, NTH, SMEM_DYN>>>();
    k2_combine<<<B_ * 8, 128>>>(b_out, out);
    dim3 g3(O_ / 128, B_, KS);
    k3_out<<<g3, 128>>>(w_out, out);
}

// round 16
// speedup vs baseline: 1.3117x; 1.0135x over previous
#include <cuda_runtime.h>
#include <cuda_fp16.h>
#include <cstdint>
#include <math.h>

// ---------------------------------------------------------------- constants
#define B_ 4
#define S_ 8192
#define D_ 1024
#define H_ 1024
#define O_ 1024

#define BM 128                 // s-rows per CTA tile
#define BN 64                  // j-cols per CTA tile (per gate; 3 gates)
#define BK 32                  // k per pipeline chunk
#define NCHUNK (D_ / BK)       // 32
#define NTH 512                // 16 warps (4 per SMSP)

#define ROWB 80                // fp16 smem row stride bytes (64 data + 16 pad)
#define A_TILE (BM * ROWB)     // 10240  (one A16 buffer)
#define B_TILE (BN * ROWB)     // 5120
#define BSTAGE (3 * B_TILE)    // 15360  (3 gates)
#define B_OFF  (2 * A_TILE)    // 20480  (A16 double buffer first)
#define SMEM_DYN (B_OFF + 4 * BSTAGE)   // 81920

#define MTILES (B_ * S_ / BM)  // 256
#define JTILES (H_ / BN)       // 16
#define MT_PER_B (S_ / BM)     // 64

// ---------------------------------------------------------------- scratch
__device__ __half g_wh[3 * H_ * D_];
__device__ float g_pacc[B_][MT_PER_B][H_];
__device__ float g_sig[B_][H_];
__device__ float g_hT[B_][H_];

// ---------------------------------------------------------------- helpers
__device__ __forceinline__ uint32_t smem_u32(const void* p) {
    uint32_t a;
    asm("{ .reg .u64 t; cvta.to.shared.u64 t, %1; cvt.u32.u64 %0, t; }"
        : "=r"(a) : "l"(p));
    return a;
}

__device__ __forceinline__ void cp_async16(uint32_t dst, const void* src) {
    size_t g = (size_t)__cvta_generic_to_global(src);
    asm volatile("cp.async.cg.shared.global [%0], [%1], 16;\n"
                 :: "r"(dst), "l"(g));
}

__device__ __forceinline__ void ldsm_x4(uint32_t* r, uint32_t addr) {
    asm volatile("ldmatrix.sync.aligned.m8n8.x4.shared.b16 {%0,%1,%2,%3}, [%4];"
                 : "=r"(r[0]), "=r"(r[1]), "=r"(r[2]), "=r"(r[3]) : "r"(addr));
}

__device__ __forceinline__ void mma16816(float* c, const uint32_t* a,
                                         uint32_t b0, uint32_t b1) {
    asm volatile(
        "mma.sync.aligned.m16n8k16.row.col.f32.f16.f16.f32 "
        "{%0,%1,%2,%3}, {%4,%5,%6,%7}, {%8,%9}, {%0,%1,%2,%3};"
        : "+f"(c[0]), "+f"(c[1]), "+f"(c[2]), "+f"(c[3])
        : "r"(a[0]), "r"(a[1]), "r"(a[2]), "r"(a[3]), "r"(b0), "r"(b1));
}

// ---------------------------------------------------------------- prep: w fp32 -> fp16 (w only)
#define NW4 (3 * H_ * D_ / 4)      // 786432

__global__ __launch_bounds__(512) void k_cvt_w(const float* __restrict__ w) {
    int base = blockIdx.x * 2048 + threadIdx.x;
#pragma unroll
    for (int v = 0; v < 4; ++v) {
        int i = base + v * 512;
        if (i >= NW4) return;
        float4 u = ((const float4*)w)[i];
        unsigned short hb[4];
        hb[0] = __half_as_ushort(__float2half_rn(u.x));
        hb[1] = __half_as_ushort(__float2half_rn(u.y));
        hb[2] = __half_as_ushort(__float2half_rn(u.z));
        hb[3] = __half_as_ushort(__float2half_rn(u.w));
        uint2 hp;
        hp.x = (uint32_t)hb[0] | ((uint32_t)hb[1] << 16);
        hp.y = (uint32_t)hb[2] | ((uint32_t)hb[3] << 16);
        ((uint2*)g_wh)[i] = hp;
    }
}

// ---------------------------------------------------------------- B stage loader (fp16 w)
__device__ __forceinline__ void load_B(uint32_t sb0, int ck, int j0, int tid) {
    const int k0 = ck * BK;
    const uint32_t bb = sb0 + B_OFF + (ck & 3) * BSTAGE;
    // 3 gates x 64 rows x 4 chunks = 768 cp.asyncs
    {
        int idx = tid;                 // 0..511, all valid
        int g = idx >> 8, rr = idx & 255;
        int r = rr >> 2, c = rr & 3;
        const void* src = g_wh + (size_t)(g * H_ + j0 + r) * D_ + k0 + c * 8;
        cp_async16(bb + g * B_TILE + r * ROWB + c * 16, src);
    }
    if (tid < 256) {
        int idx = tid + 512;           // 512..767
        int g = idx >> 8, rr = idx & 255;
        int r = rr >> 2, c = rr & 3;
        const void* src = g_wh + (size_t)(g * H_ + j0 + r) * D_ + k0 + c * 8;
        cp_async16(bb + g * B_TILE + r * ROWB + c * 16, src);
    }
    asm volatile("cp.async.commit_group;" ::: "memory");
}

// ---------------------------------------------------------------- main fused cvt+GEMM+reduce
extern __shared__ __align__(128) char dynsmem[];

__global__ __launch_bounds__(NTH, 1) void k1_mma(const float* __restrict__ x) {
    __shared__ float jacc[4][BN];

    const int tid = threadIdx.x;
    const int wid = tid >> 5;
    const int lane = tid & 31;
    const int wm = wid >> 2;            // 0..3 (32 rows each)
    const int wn = wid & 3;             // 0..3 (16 cols each)
    const int jt = blockIdx.x;          // 0..15
    const int mt = blockIdx.y;          // 0..255
    const int b = mt >> 6;
    const int mtb = mt & 63;
    const int j0 = jt * BN;

    const uint32_t sb0 = smem_u32(dynsmem);
    const size_t xrow0 = (size_t)mt * BM * D_;

    // per-thread A ownership: 8 consecutive fp32 of one row per chunk
    const int ar = tid >> 2;            // row 0..127
    const int ac = tid & 3;             // 8-float group 0..3
    const float* xp = x + xrow0 + (size_t)ar * D_ + ac * 8;
    const uint32_t a_dst_base = sb0 + ar * ROWB + ac * 16;

    float4 rA0, rA1;                    // register-held raw A fp32 (one chunk)

    float acc[3][2][2][4];
#pragma unroll
    for (int g = 0; g < 3; ++g)
#pragma unroll
        for (int mf = 0; mf < 2; ++mf)
#pragma unroll
            for (int nf = 0; nf < 2; ++nf)
#pragma unroll
                for (int q = 0; q < 4; ++q) acc[g][mf][nf][q] = 0.0f;

    // ---- prologue
    rA0 = *(const float4*)(xp + 0);               // LDG chunk 0
    rA1 = *(const float4*)(xp + 4);
    load_B(sb0, 0, j0, tid);
    load_B(sb0, 1, j0, tid);
    load_B(sb0, 2, j0, tid);
    {   // cvt chunk 0 -> A16[0]
        __half2 h0 = __floats2half2_rn(rA0.x, rA0.y);
        __half2 h1 = __floats2half2_rn(rA0.z, rA0.w);
        __half2 h2 = __floats2half2_rn(rA1.x, rA1.y);
        __half2 h3 = __floats2half2_rn(rA1.z, rA1.w);
        asm volatile("st.shared.v4.b32 [%0], {%1,%2,%3,%4};"
                     :: "r"(a_dst_base), "r"(*(uint32_t*)&h0),
                        "r"(*(uint32_t*)&h1), "r"(*(uint32_t*)&h2),
                        "r"(*(uint32_t*)&h3));
    }
    rA0 = *(const float4*)(xp + BK);              // LDG chunk 1
    rA1 = *(const float4*)(xp + BK + 4);

    const uint32_t a_rowsel = (wm * 32 + (lane & 15)) * ROWB +
                              ((lane >> 4) << 4);
    const uint32_t b_rowsel = (wn * 16 + (lane & 15)) * ROWB +
                              ((lane >> 4) << 4);

    for (int ck = 0; ck < NCHUNK; ++ck) {
        if (ck <= NCHUNK - 3) {
            asm volatile("cp.async.wait_group 2;" ::: "memory");
        } else if (ck == NCHUNK - 2) {
            asm volatile("cp.async.wait_group 1;" ::: "memory");
        } else {
            asm volatile("cp.async.wait_group 0;" ::: "memory");
        }
        __syncthreads();

        // convert chunk ck+1 (regs) -> A16[(ck+1)&1]; then LDG chunk ck+2
        if (ck + 1 < NCHUNK) {
            __half2 h0 = __floats2half2_rn(rA0.x, rA0.y);
            __half2 h1 = __floats2half2_rn(rA0.z, rA0.w);
            __half2 h2 = __floats2half2_rn(rA1.x, rA1.y);
            __half2 h3 = __floats2half2_rn(rA1.z, rA1.w);
            asm volatile("st.shared.v4.b32 [%0], {%1,%2,%3,%4};"
                         :: "r"(a_dst_base + ((ck + 1) & 1) * A_TILE),
                            "r"(*(uint32_t*)&h0), "r"(*(uint32_t*)&h1),
                            "r"(*(uint32_t*)&h2), "r"(*(uint32_t*)&h3));
        }
        if (ck + 2 < NCHUNK) {
            rA0 = *(const float4*)(xp + (ck + 2) * BK);
            rA1 = *(const float4*)(xp + (ck + 2) * BK + 4);
        }
        if (ck + 3 < NCHUNK)
            load_B(sb0, ck + 3, j0, tid);

        const uint32_t abuf = sb0 + (ck & 1) * A_TILE;
        const uint32_t bbuf = sb0 + B_OFF + (ck & 3) * BSTAGE;

#pragma unroll
        for (int ks = 0; ks < 2; ++ks) {
            const uint32_t koff = ks * 32;
            uint32_t ah[2][4];
#pragma unroll
            for (int mf = 0; mf < 2; ++mf)
                ldsm_x4(ah[mf], abuf + a_rowsel + mf * (16 * ROWB) + koff);
#pragma unroll
            for (int g = 0; g < 3; ++g) {
                uint32_t bq[4];   // r0=nf0.b0 r1=nf1.b0 r2=nf0.b1 r3=nf1.b1
                ldsm_x4(bq, bbuf + g * B_TILE + b_rowsel + koff);
#pragma unroll
                for (int mf = 0; mf < 2; ++mf) {
                    mma16816(acc[g][mf][0], ah[mf], bq[0], bq[2]);
                    mma16816(acc[g][mf][1], ah[mf], bq[1], bq[3]);
                }
            }
        }
    }

    // ---- epilogue: elementwise + reduce over s rows
    float vloc[2][2] = {{0.f, 0.f}, {0.f, 0.f}};   // [nf][q&1]
#pragma unroll
    for (int mf = 0; mf < 2; ++mf)
#pragma unroll
        for (int nf = 0; nf < 2; ++nf)
#pragma unroll
            for (int q = 0; q < 4; ++q) {
                float zf = acc[0][mf][nf][q];
                float zi = acc[1][mf][nf][q];
                float zh = acc[2][mf][nf][q];
                float R = __fdividef(1.0f + __expf(-zf),
                                     1.0f + __expf(-zi));   // exp(diff)
                float gv = (zh >= 0.0f)
                               ? (zh + 0.5f)
                               : __fdividef(1.0f, 1.0f + __expf(-zh));
                vloc[nf][q & 1] += R * gv;
                int row = wm * 32 + mf * 16 + (lane >> 2) + ((q >> 1) << 3);
                if (((mt * BM + row) & (S_ - 1)) == (S_ - 1)) {
                    int j = j0 + wn * 16 + nf * 8 + (lane & 3) * 2 + (q & 1);
                    g_sig[b][j] = __fdividef(1.0f, 1.0f + R);
                }
            }
#pragma unroll
    for (int nf = 0; nf < 2; ++nf)
#pragma unroll
        for (int q1 = 0; q1 < 2; ++q1) {
            float v = vloc[nf][q1];
            v += __shfl_xor_sync(0xffffffffu, v, 4);
            v += __shfl_xor_sync(0xffffffffu, v, 8);
            v += __shfl_xor_sync(0xffffffffu, v, 16);
            if (lane < 4) jacc[wm][wn * 16 + nf * 8 + lane * 2 + q1] = v;
        }
    __syncthreads();
    if (tid < BN)
        g_pacc[b][mtb][j0 + tid] =
            jacc[0][tid] + jacc[1][tid] + jacc[2][tid] + jacc[3][tid];
}

// ---------------------------------------------------------------- combine + out-init
__global__ __launch_bounds__(128) void k2_combine(const float* __restrict__ b_out,
                                                  float* __restrict__ out) {
    int b = blockIdx.x >> 3;
    int j = (blockIdx.x & 7) * 128 + threadIdx.x;
    float s = 0.0f;
#pragma unroll
    for (int mtb = 0; mtb < MT_PER_B; ++mtb) s += g_pacc[b][mtb][j];
    g_hT[b][j] = g_sig[b][j] * (0.5f + s);
    out[(size_t)b * O_ + j] = b_out[j];   // bias init for k3's atomics
}

// ---------------------------------------------------------------- out += hT @ w_out^T (k-split, atomic)
#define KS 16
#define KCH (H_ / KS)          // 64 k per split

__global__ __launch_bounds__(128) void k3_out(const float* __restrict__ w_out,
                                              float* __restrict__ out) {
    int o = blockIdx.x * 128 + threadIdx.x;
    int b = blockIdx.y;
    int k0 = blockIdx.z * KCH;

    __shared__ float hs[KCH];
    if (threadIdx.x < KCH) hs[threadIdx.x] = g_hT[b][k0 + threadIdx.x];
    __syncthreads();

    float acc = 0.0f;
    const float4* wr = (const float4*)(w_out + (size_t)o * H_ + k0);
#pragma unroll
    for (int q = 0; q < KCH / 4; ++q) {
        float4 w4 = wr[q];
        float4 h4 = *(const float4*)&hs[q * 4];
        acc = fmaf(w4.x, h4.x, acc);
        acc = fmaf(w4.y, h4.y, acc);
        acc = fmaf(w4.z, h4.z, acc);
        acc = fmaf(w4.w, h4.w, acc);
    }
    atomicAdd(&out[(size_t)b * O_ + o], acc);
}

// ---------------------------------------------------------------- launch
extern "C" void kernel_launch(void* const* d_in, const int* in_sizes, int n_in,
                              void* d_out, int out_size) {
    (void)in_sizes; (void)n_in; (void)out_size;
    const float* x     = (const float*)d_in[0];   // [4, 8192, 1024]
    const float* w_in  = (const float*)d_in[1];   // [3072, 1024]
    const float* w_out = (const float*)d_in[2];   // [1024, 1024]
    const float* b_out = (const float*)d_in[3];   // [1024]
    float* out = (float*)d_out;                   // [4, 1024]

    static int smem_set = 0;
    if (!smem_set) {
        cudaFuncSetAttribute(k1_mma, cudaFuncAttributeMaxDynamicSharedMemorySize,
                             SMEM_DYN);
        smem_set = 1;
    }

    k_cvt_w<<<(NW4 + 2047) / 2048, 512>>>(w_in);

    dim3 g1(JTILES, MTILES);
    k1_mma<<<g1, NTH, SMEM_DYN>>>(x);
    k2_combine<<<B_ * 8, 128>>>(b_out, out);
    dim3 g3(O_ / 128, B_, KS);
    k3_out<<<g3, 128>>>(w_out, out);
}